// round 14
// baseline (speedup 1.0000x reference)
#include <cuda_runtime.h>
#include <cstddef>

#define GRID3 256
#define NVOX  (256*256*256)
#define HTP   2     // h rows per thread
#define HSUB  4     // h subtiles per CTA (threadIdx.y)
#define HTILE (HTP*HSUB)          // 8 h rows per CTA
#define DSEG  8     // d slices per CTA
#define SLICE4 16384              // float4s per d-slice (65536/4)
#define ROW4   64                 // float4s per h-row   (256/4)

// Static device scratch (allowed; no allocation). Zero-initialized at load;
// every kernel_launch call restores it to all-zero via cleanup_kernel.
__device__ float g_vol[NVOX];

__device__ __forceinline__ float4 f4add(float4 a, float4 b) {
    return make_float4(a.x + b.x, a.y + b.y, a.z + b.z, a.w + b.w);
}
__device__ __forceinline__ float4 f4sub(float4 a, float4 b) {
    return make_float4(a.x - b.x, a.y - b.y, a.z - b.z, a.w - b.w);
}

// ---------------------------------------------------------------------------
// Scatter with fused W-blur: each point adds f to voxels (d,h,w-2..w+2).
// Two 16B-aligned vector reductions over the aligned 8-float window
// containing the 5-tap span; lanes outside the span add +0.0.
// ---------------------------------------------------------------------------
__global__ void scatter_w_kernel(const float* __restrict__ feats,
                                 const int* __restrict__ coords,
                                 int n)
{
    int i = blockIdx.x * blockDim.x + threadIdx.x;
    if (i >= n) return;
    float f = feats[i];
    int d = coords[3 * i + 0];
    int h = coords[3 * i + 1];
    int w = coords[3 * i + 2];

    int base = (w - 2) & ~3;                 // 16B-aligned quad start
    base = base < 0 ? 0 : (base > GRID3 - 8 ? GRID3 - 8 : base);

    float* p = g_vol + (((size_t)d << 16) | ((size_t)h << 8)) + base;

    float vals[8];
#pragma unroll
    for (int j = 0; j < 8; j++) {
        int idx = base + j;
        vals[j] = (idx >= w - 2 && idx <= w + 2) ? f : 0.f;
    }
    asm volatile("red.global.add.v4.f32 [%0], {%1,%2,%3,%4};"
                 :: "l"(p), "f"(vals[0]), "f"(vals[1]), "f"(vals[2]), "f"(vals[3])
                 : "memory");
    asm volatile("red.global.add.v4.f32 [%0], {%1,%2,%3,%4};"
                 :: "l"(p + 4), "f"(vals[4]), "f"(vals[5]), "f"(vals[6]), "f"(vals[7])
                 : "memory");
}

// ---------------------------------------------------------------------------
// Cleanup: re-zero exactly the spans scatter_w touched (idempotent; duplicate
// points race writing identical zeros, which is benign). Runs after blur_hd
// has consumed g_vol, restoring the all-zero invariant for the next call.
// ---------------------------------------------------------------------------
__global__ void cleanup_kernel(const int* __restrict__ coords, int n)
{
    int i = blockIdx.x * blockDim.x + threadIdx.x;
    if (i >= n) return;
    int d = coords[3 * i + 0];
    int h = coords[3 * i + 1];
    int w = coords[3 * i + 2];

    int base = (w - 2) & ~3;
    base = base < 0 ? 0 : (base > GRID3 - 8 ? GRID3 - 8 : base);

    float4* p = (float4*)(g_vol + (((size_t)d << 16) | ((size_t)h << 8)) + base);
    float4 z = make_float4(0.f, 0.f, 0.f, 0.f);
    p[0] = z;
    p[1] = z;
}

// ---------------------------------------------------------------------------
// Vectorized H-sum loader: for d-slice s, load HTP+4 h-rows (float4 at quad
// wq), zero outside the volume, and produce HTP 5-tap H-sums.
// ---------------------------------------------------------------------------
__device__ __forceinline__ void load_hs4(const float4* __restrict__ in,
                                         int s, int h0, int wq, float4* hs)
{
    float4 v[HTP + 4];
    if (s >= 0 && s < GRID3) {
        const float4* slice = in + (size_t)s * SLICE4 + wq;
#pragma unroll
        for (int r = 0; r < HTP + 4; r++) {
            int h = h0 - 2 + r;
            v[r] = (h >= 0 && h < GRID3) ? slice[(size_t)h * ROW4]
                                         : make_float4(0.f, 0.f, 0.f, 0.f);
        }
    } else {
#pragma unroll
        for (int r = 0; r < HTP + 4; r++) v[r] = make_float4(0.f, 0.f, 0.f, 0.f);
    }
    hs[0] = f4add(f4add(f4add(v[0], v[1]), f4add(v[2], v[3])), v[4]);
#pragma unroll
    for (int i = 1; i < HTP; i++)
        hs[i] = f4add(hs[i - 1], f4sub(v[i + 4], v[i - 1]));
}

// ---------------------------------------------------------------------------
// Fused H+D box blur, float4-vectorized, no shared memory. Thread = one
// 4-wide w quad x HTP h-rows; marches DSEG d-slices with a 4-deep depth ring
// of H-sums (statically rotated by full unroll).
// ---------------------------------------------------------------------------
__global__ __launch_bounds__(256) void blur_hd_kernel(const float4* __restrict__ in,
                                                      float4* __restrict__ out)
{
    int wq = threadIdx.x;                              // 0..63
    int h0 = blockIdx.x * HTILE + threadIdx.y * HTP;   // h rows of this thread
    int d0 = blockIdx.y * DSEG;

    float4 ring[4][HTP];

    // Warmup: slices d0-2 .. d0+1
#pragma unroll
    for (int k = 0; k < 4; k++)
        load_hs4(in, d0 - 2 + k, h0, wq, ring[k]);

    // Steady: step t loads slice d0+2+t, emits output slice d0+t.
#pragma unroll
    for (int t = 0; t < DSEG; t++) {
        float4 hs[HTP];
        load_hs4(in, d0 + 2 + t, h0, wq, hs);
        float4* o = out + (size_t)(d0 + t) * SLICE4 + (size_t)h0 * ROW4 + wq;
#pragma unroll
        for (int i = 0; i < HTP; i++) {
            o[(size_t)i * ROW4] =
                f4add(f4add(f4add(ring[0][i], ring[1][i]),
                            f4add(ring[2][i], ring[3][i])), hs[i]);
            ring[t & 3][i] = hs[i];    // static after unroll: register rotation
        }
    }
}

// ---------------------------------------------------------------------------
// Launch: scatter+W (->vol) -> fused HD (vol -> d_out) -> cleanup (vol -> 0)
// vol is all-zero on entry (zero-init at load; cleanup restores it each call).
// All default-stream, graph-capturable, allocation-free.
// ---------------------------------------------------------------------------
extern "C" void kernel_launch(void* const* d_in, const int* in_sizes, int n_in,
                              void* d_out, int out_size)
{
    const float* feats  = (const float*)d_in[0];
    const int*   coords = (const int*)d_in[1];
    int n = in_sizes[0];
    float4* out = (float4*)d_out;

    float* vol = nullptr;
    cudaGetSymbolAddress((void**)&vol, g_vol);

    scatter_w_kernel<<<(n + 255) / 256, 256>>>(feats, coords, n);

    dim3 blockHD(64, 4);
    dim3 gridHD(GRID3 / HTILE, GRID3 / DSEG);
    blur_hd_kernel<<<gridHD, blockHD>>>((const float4*)vol, out);

    cleanup_kernel<<<(n + 255) / 256, 256>>>(coords, n);
}

// round 16
// speedup vs baseline: 1.0235x; 1.0235x over previous
#include <cuda_runtime.h>
#include <cstddef>

#define GRID3 256
#define NVOX  (256*256*256)
#define HTP   2     // h rows per thread
#define HSUB  4     // h subtiles per CTA (threadIdx.y)
#define HTILE (HTP*HSUB)          // 8 h rows per CTA
#define DSEG  8     // d slices per CTA
#define SLICE4 16384              // float4s per d-slice (65536/4)
#define ROW4   64                 // float4s per h-row   (256/4)

// Static device scratch (allowed; no allocation)
__device__ float g_vol[NVOX];

__device__ __forceinline__ float4 f4add(float4 a, float4 b) {
    return make_float4(a.x + b.x, a.y + b.y, a.z + b.z, a.w + b.w);
}
__device__ __forceinline__ float4 f4sub(float4 a, float4 b) {
    return make_float4(a.x - b.x, a.y - b.y, a.z - b.z, a.w - b.w);
}

// ---------------------------------------------------------------------------
// Scatter with fused W-blur: each point adds f to voxels (d,h,w-2..w+2).
// Two 16B-aligned vector reductions over the aligned 8-float window
// containing the 5-tap span; lanes outside the span add +0.0.
// ---------------------------------------------------------------------------
__global__ void scatter_w_kernel(const float* __restrict__ feats,
                                 const int* __restrict__ coords,
                                 int n)
{
    int i = blockIdx.x * blockDim.x + threadIdx.x;
    if (i >= n) return;
    float f = feats[i];
    int d = coords[3 * i + 0];
    int h = coords[3 * i + 1];
    int w = coords[3 * i + 2];

    int base = (w - 2) & ~3;                 // 16B-aligned quad start
    base = base < 0 ? 0 : (base > GRID3 - 8 ? GRID3 - 8 : base);

    float* p = g_vol + (((size_t)d << 16) | ((size_t)h << 8)) + base;

    float vals[8];
#pragma unroll
    for (int j = 0; j < 8; j++) {
        int idx = base + j;
        vals[j] = (idx >= w - 2 && idx <= w + 2) ? f : 0.f;
    }
    asm volatile("red.global.add.v4.f32 [%0], {%1,%2,%3,%4};"
                 :: "l"(p), "f"(vals[0]), "f"(vals[1]), "f"(vals[2]), "f"(vals[3])
                 : "memory");
    asm volatile("red.global.add.v4.f32 [%0], {%1,%2,%3,%4};"
                 :: "l"(p + 4), "f"(vals[4]), "f"(vals[5]), "f"(vals[6]), "f"(vals[7])
                 : "memory");
}

// ---------------------------------------------------------------------------
// Vectorized H-sum loader: for d-slice s, load HTP+4 h-rows (float4 at quad
// wq), zero outside the volume, and produce HTP 5-tap H-sums.
// ---------------------------------------------------------------------------
__device__ __forceinline__ void load_hs4(const float4* __restrict__ in,
                                         int s, int h0, int wq, float4* hs)
{
    float4 v[HTP + 4];
    if (s >= 0 && s < GRID3) {
        const float4* slice = in + (size_t)s * SLICE4 + wq;
#pragma unroll
        for (int r = 0; r < HTP + 4; r++) {
            int h = h0 - 2 + r;
            v[r] = (h >= 0 && h < GRID3) ? slice[(size_t)h * ROW4]
                                         : make_float4(0.f, 0.f, 0.f, 0.f);
        }
    } else {
#pragma unroll
        for (int r = 0; r < HTP + 4; r++) v[r] = make_float4(0.f, 0.f, 0.f, 0.f);
    }
    hs[0] = f4add(f4add(f4add(v[0], v[1]), f4add(v[2], v[3])), v[4]);
#pragma unroll
    for (int i = 1; i < HTP; i++)
        hs[i] = f4add(hs[i - 1], f4sub(v[i + 4], v[i - 1]));
}

// ---------------------------------------------------------------------------
// Fused H+D box blur, float4-vectorized, no shared memory. Thread = one
// 4-wide w quad x HTP h-rows; marches DSEG d-slices with a 4-deep depth ring
// of H-sums (statically rotated by full unroll).
// ---------------------------------------------------------------------------
__global__ __launch_bounds__(256) void blur_hd_kernel(const float4* __restrict__ in,
                                                      float4* __restrict__ out)
{
    int wq = threadIdx.x;                              // 0..63
    int h0 = blockIdx.x * HTILE + threadIdx.y * HTP;   // h rows of this thread
    int d0 = blockIdx.y * DSEG;

    float4 ring[4][HTP];

    // Warmup: slices d0-2 .. d0+1
#pragma unroll
    for (int k = 0; k < 4; k++)
        load_hs4(in, d0 - 2 + k, h0, wq, ring[k]);

    // Steady: step t loads slice d0+2+t, emits output slice d0+t.
#pragma unroll
    for (int t = 0; t < DSEG; t++) {
        float4 hs[HTP];
        load_hs4(in, d0 + 2 + t, h0, wq, hs);
        float4* o = out + (size_t)(d0 + t) * SLICE4 + (size_t)h0 * ROW4 + wq;
#pragma unroll
        for (int i = 0; i < HTP; i++) {
            o[(size_t)i * ROW4] =
                f4add(f4add(f4add(ring[0][i], ring[1][i]),
                            f4add(ring[2][i], ring[3][i])), hs[i]);
            ring[t & 3][i] = hs[i];    // static after unroll: register rotation
        }
    }
}

// ---------------------------------------------------------------------------
// Launch: memset vol -> scatter+W (->vol) -> fused HD (vol -> d_out)
// All default-stream, graph-capturable, allocation-free.
// ---------------------------------------------------------------------------
extern "C" void kernel_launch(void* const* d_in, const int* in_sizes, int n_in,
                              void* d_out, int out_size)
{
    const float* feats  = (const float*)d_in[0];
    const int*   coords = (const int*)d_in[1];
    int n = in_sizes[0];
    float4* out = (float4*)d_out;

    float* vol = nullptr;
    cudaGetSymbolAddress((void**)&vol, g_vol);

    cudaMemsetAsync(vol, 0, (size_t)NVOX * sizeof(float));

    scatter_w_kernel<<<(n + 255) / 256, 256>>>(feats, coords, n);

    dim3 blockHD(64, 4);
    dim3 gridHD(GRID3 / HTILE, GRID3 / DSEG);
    blur_hd_kernel<<<gridHD, blockHD>>>((const float4*)vol, out);
}